// round 4
// baseline (speedup 1.0000x reference)
#include <cuda_runtime.h>
#include <math.h>
#include <stdint.h>

#define BB 8
#define TT 2048
#define DD 1024
#define EE 1024

#define A_STRIDE 44    // 128x32 fp32 tile rows, 176B (16B-aligned), conflict-free frags
#define B_STRIDE 136   // 32x128 fp32 tile rows, 544B (16B-aligned), conflict-free frags

#define NCB 136        // causal 128x128 blocks per batch: 16*17/2

// -------- scratch (device globals; allocation-free) --------
__device__ float g_Q[(size_t)BB * TT * EE];
__device__ float g_K[(size_t)BB * TT * EE];
__device__ float g_V[(size_t)BB * TT * EE];
__device__ float g_S[(size_t)BB * TT * TT];
__device__ unsigned g_max_u[BB];
__device__ float g_psum[BB * NCB];
__device__ float g_inv_sum[BB];

__device__ __forceinline__ unsigned f2mono(float f) {
    unsigned u = __float_as_uint(f);
    return (u & 0x80000000u) ? ~u : (u | 0x80000000u);
}
__device__ __forceinline__ float mono2f(unsigned v) {
    return (v & 0x80000000u) ? __uint_as_float(v ^ 0x80000000u)
                             : __uint_as_float(~v);
}

__global__ void init_kernel() {
    if (threadIdx.x < BB) g_max_u[threadIdx.x] = 0u;
}

// -------- tf32 / mma / cp.async helpers --------
__device__ __forceinline__ unsigned f2tf(float f) {
    unsigned u;
    asm("cvt.rna.tf32.f32 %0, %1;" : "=r"(u) : "f"(f));
    return u;
}

__device__ __forceinline__ void mma8(float* c, unsigned a0, unsigned a1,
                                     unsigned a2, unsigned a3,
                                     unsigned b0, unsigned b1) {
    asm("mma.sync.aligned.m16n8k8.row.col.f32.tf32.tf32.f32 "
        "{%0,%1,%2,%3}, {%4,%5,%6,%7}, {%8,%9}, {%0,%1,%2,%3};"
        : "+f"(c[0]), "+f"(c[1]), "+f"(c[2]), "+f"(c[3])
        : "r"(a0), "r"(a1), "r"(a2), "r"(a3), "r"(b0), "r"(b1));
}

__device__ __forceinline__ void cpasync16(uint32_t dst, const float* src) {
    asm volatile("cp.async.ca.shared.global [%0], [%1], 16;"
                 :: "r"(dst), "l"(src));
}
__device__ __forceinline__ void cpcommit() {
    asm volatile("cp.async.commit_group;");
}
__device__ __forceinline__ void cpwait0() {
    asm volatile("cp.async.wait_group 0;");
}

// async fill: A-shaped tile (128 rows x 32 floats), row stride A_STRIDE
__device__ __forceinline__ void fillA_async(uint32_t dstu, const float* src,
                                            int lda, int tid) {
#pragma unroll
    for (int it = 0; it < 4; ++it) {
        int vidx = tid + it * 256;
        int row = vidx >> 3;
        int kc = (vidx & 7) * 4;
        cpasync16(dstu + (uint32_t)(row * A_STRIDE + kc) * 4u,
                  src + (size_t)row * lda + kc);
    }
}

// async fill: B-shaped tile (32 rows x 128 floats), row stride B_STRIDE
__device__ __forceinline__ void fillB_async(uint32_t dstu, const float* src,
                                            int ldb, int tid) {
#pragma unroll
    for (int it = 0; it < 4; ++it) {
        int vidx = tid + it * 256;
        int row = vidx >> 5;
        int nc = (vidx & 31) * 4;
        cpasync16(dstu + (uint32_t)(row * B_STRIDE + nc) * 4u,
                  src + (size_t)row * ldb + nc);
    }
}

// mma on one 32-deep k-tile; A fp32 [128 x 32]@A_STRIDE, B fp32 [32 x 128]@B_STRIDE
__device__ __forceinline__ void mma_tileB(const float* As, const float* Bs,
                                          float acc[4][4][4], int wm, int wn,
                                          int g, int tg) {
#pragma unroll
    for (int kk = 0; kk < 32; kk += 8) {
        unsigned a[4][4];
#pragma unroll
        for (int mi = 0; mi < 4; ++mi) {
            const float* p = &As[(wm * 64 + mi * 16 + g) * A_STRIDE + kk + tg];
            a[mi][0] = f2tf(p[0]);
            a[mi][1] = f2tf(p[8 * A_STRIDE]);
            a[mi][2] = f2tf(p[4]);
            a[mi][3] = f2tf(p[8 * A_STRIDE + 4]);
        }
        unsigned b[4][2];
#pragma unroll
        for (int ni = 0; ni < 4; ++ni) {
            const float* p = &Bs[(kk + tg) * B_STRIDE + wn * 32 + ni * 8 + g];
            b[ni][0] = f2tf(p[0]);
            b[ni][1] = f2tf(p[4 * B_STRIDE]);
        }
#pragma unroll
        for (int mi = 0; mi < 4; ++mi)
#pragma unroll
            for (int ni = 0; ni < 4; ++ni)
                mma8(acc[mi][ni], a[mi][0], a[mi][1], a[mi][2], a[mi][3],
                     b[ni][0], b[ni][1]);
    }
}

// mma with B given as K-tile in A layout (row = n, col = k): transpose folded in
__device__ __forceinline__ void mma_tileT(const float* As, const float* Ks,
                                          float acc[4][4][4], int wm, int wn,
                                          int g, int tg) {
#pragma unroll
    for (int kk = 0; kk < 32; kk += 8) {
        unsigned a[4][4];
#pragma unroll
        for (int mi = 0; mi < 4; ++mi) {
            const float* p = &As[(wm * 64 + mi * 16 + g) * A_STRIDE + kk + tg];
            a[mi][0] = f2tf(p[0]);
            a[mi][1] = f2tf(p[8 * A_STRIDE]);
            a[mi][2] = f2tf(p[4]);
            a[mi][3] = f2tf(p[8 * A_STRIDE + 4]);
        }
        unsigned b[4][2];
#pragma unroll
        for (int ni = 0; ni < 4; ++ni) {
            const float* p = &Ks[(wn * 32 + ni * 8 + g) * A_STRIDE + kk + tg];
            b[ni][0] = f2tf(p[0]);
            b[ni][1] = f2tf(p[4]);
        }
#pragma unroll
        for (int mi = 0; mi < 4; ++mi)
#pragma unroll
            for (int ni = 0; ni < 4; ++ni)
                mma8(acc[mi][ni], a[mi][0], a[mi][1], a[mi][2], a[mi][3],
                     b[ni][0], b[ni][1]);
    }
}

#define A_WORDS (128 * A_STRIDE)   // 5632
#define B_WORDS (32 * B_STRIDE)    // 4352
#define PROJ_SMEM_BYTES (2 * (A_WORDS + B_WORDS) * 4)   // 79872
#define SCORES_SMEM_BYTES (4 * A_WORDS * 4)             // 90112

// ---------------------------------------------------------------------------
// Projection: C[16384,1024] = A @ W + bias (2-stage cp.async pipeline)
// ---------------------------------------------------------------------------
__global__ __launch_bounds__(256, 2) void proj_kernel(
    const float* __restrict__ A, const float* __restrict__ W,
    const float* __restrict__ bias, int sel)
{
    extern __shared__ __align__(16) float smem[];
    float* Abuf[2] = {smem, smem + A_WORDS};
    float* Bbuf[2] = {smem + 2 * A_WORDS, smem + 2 * A_WORDS + B_WORDS};
    uint32_t su = (uint32_t)__cvta_generic_to_shared(smem);
    uint32_t Au[2] = {su, su + A_WORDS * 4};
    uint32_t Bu[2] = {su + 2 * A_WORDS * 4, su + (2 * A_WORDS + B_WORDS) * 4};

    float* __restrict__ C = (sel == 0) ? g_Q : (sel == 1) ? g_K : g_V;

    const int tid = threadIdx.x;
    const int warp = tid >> 5, lane = tid & 31;
    const int g = lane >> 2, tg = lane & 3;
    const int wm = warp >> 2, wn = warp & 3;
    const int m0 = blockIdx.y * 128, n0 = blockIdx.x * 128;

    const float* Ab = A + (size_t)m0 * DD;
    const float* Wb = W + n0;

    float acc[4][4][4] = {};

    fillA_async(Au[0], Ab, DD, tid);
    fillB_async(Bu[0], Wb, EE, tid);
    cpcommit();

    const int NK = DD / 32;
    for (int kt = 0; kt < NK; ++kt) {
        cpwait0();
        __syncthreads();
        if (kt + 1 < NK) {
            int k0 = (kt + 1) * 32;
            fillA_async(Au[(kt + 1) & 1], Ab + k0, DD, tid);
            fillB_async(Bu[(kt + 1) & 1], Wb + (size_t)k0 * EE, EE, tid);
        }
        cpcommit();
        mma_tileB(Abuf[kt & 1], Bbuf[kt & 1], acc, wm, wn, g, tg);
        __syncthreads();
    }

#pragma unroll
    for (int mi = 0; mi < 4; ++mi) {
        int r0 = m0 + wm * 64 + mi * 16 + g;
#pragma unroll
        for (int ni = 0; ni < 4; ++ni) {
            int c = n0 + wn * 32 + ni * 8 + 2 * tg;
            float2 b2 = *reinterpret_cast<const float2*>(bias + c);
            float2 v0 = make_float2(acc[mi][ni][0] + b2.x, acc[mi][ni][1] + b2.y);
            float2 v1 = make_float2(acc[mi][ni][2] + b2.x, acc[mi][ni][3] + b2.y);
            *reinterpret_cast<float2*>(&C[(size_t)r0 * EE + c]) = v0;
            *reinterpret_cast<float2*>(&C[(size_t)(r0 + 8) * EE + c]) = v1;
        }
    }
}

// ---------------------------------------------------------------------------
// Scores: S = (Q @ K^T)/32, causal blocks only; block max -> atomicMax.
// ---------------------------------------------------------------------------
__global__ __launch_bounds__(256, 2) void scores_kernel()
{
    const int bz = blockIdx.z;
    const int t0 = blockIdx.y * 128, s0 = blockIdx.x * 128;
    if (s0 > t0 + 127) return;  // fully masked: never read downstream

    extern __shared__ __align__(16) float smem[];
    float* Abuf[2] = {smem, smem + A_WORDS};
    float* Kbuf[2] = {smem + 2 * A_WORDS, smem + 3 * A_WORDS};
    uint32_t su = (uint32_t)__cvta_generic_to_shared(smem);
    uint32_t Au[2] = {su, su + A_WORDS * 4};
    uint32_t Ku[2] = {su + 2 * A_WORDS * 4, su + 3 * A_WORDS * 4};

    const int tid = threadIdx.x;
    const int warp = tid >> 5, lane = tid & 31;
    const int g = lane >> 2, tg = lane & 3;
    const int wm = warp >> 2, wn = warp & 3;

    float* __restrict__ S = g_S + (size_t)bz * TT * TT;
    const float* Qb = g_Q + (size_t)bz * TT * EE + (size_t)t0 * EE;
    const float* Kb = g_K + (size_t)bz * TT * EE + (size_t)s0 * EE;

    float acc[4][4][4] = {};

    fillA_async(Au[0], Qb, EE, tid);
    fillA_async(Ku[0], Kb, EE, tid);
    cpcommit();

    const int NK = EE / 32;
    for (int kt = 0; kt < NK; ++kt) {
        cpwait0();
        __syncthreads();
        if (kt + 1 < NK) {
            int k0 = (kt + 1) * 32;
            fillA_async(Au[(kt + 1) & 1], Qb + k0, EE, tid);
            fillA_async(Ku[(kt + 1) & 1], Kb + k0, EE, tid);
        }
        cpcommit();
        mma_tileT(Abuf[kt & 1], Kbuf[kt & 1], acc, wm, wn, g, tg);
        __syncthreads();
    }

    float lmax = -3.4e38f;
#pragma unroll
    for (int mi = 0; mi < 4; ++mi) {
        int r0 = t0 + wm * 64 + mi * 16 + g;
#pragma unroll
        for (int ni = 0; ni < 4; ++ni) {
            int c = s0 + wn * 32 + ni * 8 + 2 * tg;
#pragma unroll
            for (int q = 0; q < 4; ++q) {
                int r = r0 + (q >> 1) * 8;
                int cc = c + (q & 1);
                float v;
                if (cc <= r) {
                    v = acc[mi][ni][q] * 0.03125f;
                    lmax = fmaxf(lmax, v);
                } else {
                    v = -1e30f;
                }
                S[(size_t)r * TT + cc] = v;
            }
        }
    }

    __shared__ float red[256];
    red[tid] = lmax;
    __syncthreads();
    for (int st = 128; st > 0; st >>= 1) {
        if (tid < st) red[tid] = fmaxf(red[tid], red[tid + st]);
        __syncthreads();
    }
    if (tid == 0) atomicMax(&g_max_u[bz], f2mono(red[0]));
}

// ---------------------------------------------------------------------------
// exp(S - m) in place over causal blocks only + deterministic partial sums.
// grid = (NCB, BB); triangular decode of block index.
// ---------------------------------------------------------------------------
__global__ __launch_bounds__(256) void exp_kernel()
{
    const int bz = blockIdx.y;
    const int l = blockIdx.x;
    int tb = (int)((sqrtf(8.0f * l + 1.0f) - 1.0f) * 0.5f);
    while ((tb + 1) * (tb + 2) / 2 <= l) ++tb;
    while (tb * (tb + 1) / 2 > l) --tb;
    const int sb = l - tb * (tb + 1) / 2;
    const int t0 = tb * 128, s0 = sb * 128;

    const float m = mono2f(g_max_u[bz]);
    float* __restrict__ S = g_S + (size_t)bz * TT * TT;

    float lsum = 0.0f;
#pragma unroll
    for (int it = 0; it < 16; ++it) {
        int vidx = threadIdx.x + it * 256;
        int r = vidx >> 5, c = (vidx & 31) * 4;
        float4* p = reinterpret_cast<float4*>(&S[(size_t)(t0 + r) * TT + s0 + c]);
        float4 v = *p;
        v.x = expf(v.x - m);
        v.y = expf(v.y - m);
        v.z = expf(v.z - m);
        v.w = expf(v.w - m);
        *p = v;
        lsum += (v.x + v.y) + (v.z + v.w);
    }

    __shared__ float red[256];
    red[threadIdx.x] = lsum;
    __syncthreads();
    for (int st = 128; st > 0; st >>= 1) {
        if (threadIdx.x < st) red[threadIdx.x] += red[threadIdx.x + st];
        __syncthreads();
    }
    if (threadIdx.x == 0) g_psum[bz * NCB + l] = red[0];
}

__global__ __launch_bounds__(256) void reduce_kernel()
{
    const int bz = blockIdx.x;
    float s = 0.0f;
    for (int i = threadIdx.x; i < NCB; i += 256) s += g_psum[bz * NCB + i];
    __shared__ float red[256];
    red[threadIdx.x] = s;
    __syncthreads();
    for (int st = 128; st > 0; st >>= 1) {
        if (threadIdx.x < st) red[threadIdx.x] += red[threadIdx.x + st];
        __syncthreads();
    }
    if (threadIdx.x == 0) g_inv_sum[bz] = 1.0f / red[0];
}

// ---------------------------------------------------------------------------
// Output: O = (E @ V) * inv_sum; k-loop truncated at diagonal.
// ---------------------------------------------------------------------------
__global__ __launch_bounds__(256, 2) void out_kernel(float* __restrict__ O)
{
    const int bz = blockIdx.z;
    const int t0 = blockIdx.y * 128, n0 = blockIdx.x * 128;

    extern __shared__ __align__(16) float smem[];
    float* Abuf[2] = {smem, smem + A_WORDS};
    float* Bbuf[2] = {smem + 2 * A_WORDS, smem + 2 * A_WORDS + B_WORDS};
    uint32_t su = (uint32_t)__cvta_generic_to_shared(smem);
    uint32_t Au[2] = {su, su + A_WORDS * 4};
    uint32_t Bu[2] = {su + 2 * A_WORDS * 4, su + (2 * A_WORDS + B_WORDS) * 4};

    const int tid = threadIdx.x;
    const int warp = tid >> 5, lane = tid & 31;
    const int g = lane >> 2, tg = lane & 3;
    const int wm = warp >> 2, wn = warp & 3;

    const float* Eb = g_S + (size_t)bz * TT * TT + (size_t)t0 * TT;
    const float* Vb = g_V + (size_t)bz * TT * EE + n0;
    const float inv = g_inv_sum[bz];

    float acc[4][4][4] = {};

    fillA_async(Au[0], Eb, TT, tid);
    fillB_async(Bu[0], Vb, EE, tid);
    cpcommit();

    const int NK = (t0 + 128) / 32;
    for (int kt = 0; kt < NK; ++kt) {
        cpwait0();
        __syncthreads();
        if (kt + 1 < NK) {
            int k0 = (kt + 1) * 32;
            fillA_async(Au[(kt + 1) & 1], Eb + k0, TT, tid);
            fillB_async(Bu[(kt + 1) & 1], Vb + (size_t)k0 * EE, EE, tid);
        }
        cpcommit();
        mma_tileB(Abuf[kt & 1], Bbuf[kt & 1], acc, wm, wn, g, tg);
        __syncthreads();
    }

#pragma unroll
    for (int mi = 0; mi < 4; ++mi) {
        int r0 = t0 + wm * 64 + mi * 16 + g;
#pragma unroll
        for (int ni = 0; ni < 4; ++ni) {
            int c = n0 + wn * 32 + ni * 8 + 2 * tg;
            float2 v0 = make_float2(acc[mi][ni][0] * inv, acc[mi][ni][1] * inv);
            float2 v1 = make_float2(acc[mi][ni][2] * inv, acc[mi][ni][3] * inv);
            *reinterpret_cast<float2*>(&O[((size_t)bz * TT + r0) * EE + c]) = v0;
            *reinterpret_cast<float2*>(&O[((size_t)bz * TT + r0 + 8) * EE + c]) = v1;
        }
    }
}

// ---------------------------------------------------------------------------
extern "C" void kernel_launch(void* const* d_in, const int* in_sizes, int n_in,
                              void* d_out, int out_size)
{
    const float* x  = (const float*)d_in[0];
    const float* Wq = (const float*)d_in[1];
    const float* bq = (const float*)d_in[2];
    const float* Wk = (const float*)d_in[3];
    const float* bk = (const float*)d_in[4];
    const float* Wv = (const float*)d_in[5];
    const float* bv = (const float*)d_in[6];
    float* out = (float*)d_out;

    static bool attr_done = false;
    if (!attr_done) {
        cudaFuncSetAttribute(proj_kernel,
            cudaFuncAttributeMaxDynamicSharedMemorySize, PROJ_SMEM_BYTES);
        cudaFuncSetAttribute(scores_kernel,
            cudaFuncAttributeMaxDynamicSharedMemorySize, SCORES_SMEM_BYTES);
        cudaFuncSetAttribute(out_kernel,
            cudaFuncAttributeMaxDynamicSharedMemorySize, PROJ_SMEM_BYTES);
        attr_done = true;
    }

    init_kernel<<<1, 32>>>();

    dim3 pgrid(EE / 128, (BB * TT) / 128);
    proj_kernel<<<pgrid, 256, PROJ_SMEM_BYTES>>>(x, Wq, bq, 0);
    proj_kernel<<<pgrid, 256, PROJ_SMEM_BYTES>>>(x, Wk, bk, 1);
    proj_kernel<<<pgrid, 256, PROJ_SMEM_BYTES>>>(x, Wv, bv, 2);

    dim3 sgrid(TT / 128, TT / 128, BB);
    scores_kernel<<<sgrid, 256, SCORES_SMEM_BYTES>>>();

    exp_kernel<<<dim3(NCB, BB), 256>>>();
    reduce_kernel<<<BB, 256>>>();

    dim3 ogrid(EE / 128, TT / 128, BB);
    out_kernel<<<ogrid, 256, PROJ_SMEM_BYTES>>>(out);
}

// round 9
// speedup vs baseline: 2.3604x; 2.3604x over previous
#include <cuda_runtime.h>
#include <cuda_fp16.h>
#include <math.h>
#include <stdint.h>

#define BB 8
#define TT 2048
#define DD 1024
#define EE 1024
#define NCB 136          // causal 128x128 blocks per batch

#define RHB 80           // bytes per smem tile row (32 halves data + pad)
#define TILE_B 10240u    // 128 rows * 80B

// -------- scratch (device globals; allocation-free) --------
__device__ half  g_Xh [(size_t)BB * TT * DD];
__device__ half  g_WTh[(size_t)3 * DD * EE];
__device__ half  g_Qh [(size_t)BB * TT * EE];
__device__ half  g_Kh [(size_t)BB * TT * EE];
__device__ half  g_Vh [(size_t)BB * TT * EE];
__device__ half  g_VTh[(size_t)BB * EE * TT];
__device__ float g_S  [(size_t)BB * TT * TT];
__device__ half  g_Eh [(size_t)BB * TT * TT];
__device__ unsigned g_max_u[BB];
__device__ float g_psum[BB * NCB];
__device__ float g_inv_sum[BB];

// -------- helpers --------
__device__ __forceinline__ unsigned f2mono(float f) {
    unsigned u = __float_as_uint(f);
    return (u & 0x80000000u) ? ~u : (u | 0x80000000u);
}
__device__ __forceinline__ float mono2f(unsigned v) {
    return (v & 0x80000000u) ? __uint_as_float(v ^ 0x80000000u)
                             : __uint_as_float(~v);
}
__device__ __forceinline__ uint32_t s2u(const void* p) {
    return (uint32_t)__cvta_generic_to_shared(p);
}
__device__ __forceinline__ void cpasync16(uint32_t dst, const void* src) {
    asm volatile("cp.async.cg.shared.global [%0], [%1], 16;" :: "r"(dst), "l"(src));
}
__device__ __forceinline__ void cpcommit() {
    asm volatile("cp.async.commit_group;" ::: "memory");
}
__device__ __forceinline__ void cpwait0() {
    asm volatile("cp.async.wait_group 0;" ::: "memory");
}

#define LDSM4(r0, r1, r2, r3, addr) \
    asm volatile("ldmatrix.sync.aligned.m8n8.x4.shared.b16 {%0,%1,%2,%3}, [%4];" \
        : "=r"(r0), "=r"(r1), "=r"(r2), "=r"(r3) : "r"(addr))

__device__ __forceinline__ void mma16816(float* c, unsigned a0, unsigned a1,
                                         unsigned a2, unsigned a3,
                                         unsigned b0, unsigned b1) {
    asm volatile(
        "mma.sync.aligned.m16n8k16.row.col.f32.f16.f16.f32 "
        "{%0,%1,%2,%3}, {%4,%5,%6,%7}, {%8,%9}, {%0,%1,%2,%3};"
        : "+f"(c[0]), "+f"(c[1]), "+f"(c[2]), "+f"(c[3])
        : "r"(a0), "r"(a1), "r"(a2), "r"(a3), "r"(b0), "r"(b1));
}

// fill one 128x32-half tile (rows RHB bytes apart), coalesced 16B chunks
__device__ __forceinline__ void fill_tile(uint32_t dst, const half* src,
                                          int lds, int tid) {
#pragma unroll
    for (int it = 0; it < 2; ++it) {
        int idx = tid + it * 256;           // 0..511
        int row = idx >> 2, c = idx & 3;    // 4 x 16B per row
        cpasync16(dst + (uint32_t)(row * RHB + c * 16),
                  src + (size_t)row * lds + c * 8);
    }
}

// 2-stage pipelined fp16 GEMM body: 128x128 CTA tile, k-tile 32.
// smem layout: [A0 | B0 | A1 | B1], each TILE_B bytes.
__device__ __forceinline__ void gemm_body(
    const half* __restrict__ A0, int lda,
    const half* __restrict__ B0, int ldb,
    int NK, uint32_t su, float acc[4][4][4], int tid)
{
    const int warp = tid >> 5, lane = tid & 31;
    const int wm = warp >> 2, wn = warp & 3;
    const uint32_t aoff = (uint32_t)((wm * 64 + (lane & 15)) * RHB + (lane >> 4) * 16);
    const uint32_t boff = (uint32_t)((wn * 32 + (lane & 7) + ((lane >> 4) << 3)) * RHB
                                     + ((lane >> 3) & 1) * 16);

    fill_tile(su, A0, lda, tid);
    fill_tile(su + TILE_B, B0, ldb, tid);
    cpcommit();

    for (int kt = 0; kt < NK; ++kt) {
        cpwait0();
        __syncthreads();
        if (kt + 1 < NK) {
            uint32_t nb = su + (uint32_t)((kt + 1) & 1) * (2 * TILE_B);
            fill_tile(nb, A0 + (size_t)(kt + 1) * 32, lda, tid);
            fill_tile(nb + TILE_B, B0 + (size_t)(kt + 1) * 32, ldb, tid);
        }
        cpcommit();

        uint32_t As = su + (uint32_t)(kt & 1) * (2 * TILE_B);
        uint32_t Bs = As + TILE_B;
#pragma unroll
        for (int ks = 0; ks < 2; ++ks) {
            unsigned a[4][4];
#pragma unroll
            for (int mi = 0; mi < 4; ++mi)
                LDSM4(a[mi][0], a[mi][1], a[mi][2], a[mi][3],
                      As + aoff + (uint32_t)(mi * 16 * RHB + ks * 32));
            unsigned b[2][4];
#pragma unroll
            for (int np = 0; np < 2; ++np)
                LDSM4(b[np][0], b[np][1], b[np][2], b[np][3],
                      Bs + boff + (uint32_t)(np * 16 * RHB + ks * 32));
#pragma unroll
            for (int mi = 0; mi < 4; ++mi)
#pragma unroll
                for (int ni = 0; ni < 4; ++ni)
                    mma16816(acc[mi][ni],
                             a[mi][0], a[mi][1], a[mi][2], a[mi][3],
                             b[ni >> 1][(ni & 1) * 2], b[ni >> 1][(ni & 1) * 2 + 1]);
        }
        __syncthreads();
    }
}

// ---------------------------------------------------------------------------
// prep kernels
// ---------------------------------------------------------------------------
__global__ void init_kernel() {
    if (threadIdx.x < BB) g_max_u[threadIdx.x] = 0u;
}

__global__ __launch_bounds__(256) void conv_x(const float* __restrict__ x) {
    size_t i = ((size_t)blockIdx.x * 256 + threadIdx.x) * 8;
    float4 v0 = *reinterpret_cast<const float4*>(x + i);
    float4 v1 = *reinterpret_cast<const float4*>(x + i + 4);
    half2 h[4];
    h[0] = __floats2half2_rn(v0.x, v0.y);
    h[1] = __floats2half2_rn(v0.z, v0.w);
    h[2] = __floats2half2_rn(v1.x, v1.y);
    h[3] = __floats2half2_rn(v1.z, v1.w);
    *reinterpret_cast<uint4*>(g_Xh + i) = *reinterpret_cast<uint4*>(h);
}

// W^T as half: g_WTh[z][n][k] = (half)W_z[k][n]
__global__ __launch_bounds__(256) void transW_kernel(
    const float* __restrict__ W0, const float* __restrict__ W1,
    const float* __restrict__ W2)
{
    const float* W = (blockIdx.z == 0) ? W0 : (blockIdx.z == 1) ? W1 : W2;
    half* WT = g_WTh + (size_t)blockIdx.z * DD * EE;
    __shared__ float tile[32][33];
    int tx = threadIdx.x & 31, ty = threadIdx.x >> 5;
    int k0 = blockIdx.y * 32, n0 = blockIdx.x * 32;
#pragma unroll
    for (int j = 0; j < 4; ++j)
        tile[ty + j * 8][tx] = W[(size_t)(k0 + ty + j * 8) * EE + n0 + tx];
    __syncthreads();
#pragma unroll
    for (int j = 0; j < 4; ++j)
        WT[(size_t)(n0 + ty + j * 8) * DD + k0 + tx] = __float2half(tile[tx][ty + j * 8]);
}

// V^T half: g_VTh[b][n][t] = g_Vh[b][t][n]
__global__ __launch_bounds__(256) void transV_kernel()
{
    const half* V = g_Vh + (size_t)blockIdx.z * TT * EE;
    half* VT = g_VTh + (size_t)blockIdx.z * EE * TT;
    __shared__ half tile[32][34];
    int tx = threadIdx.x & 31, ty = threadIdx.x >> 5;
    int t0 = blockIdx.x * 32, n0 = blockIdx.y * 32;
#pragma unroll
    for (int j = 0; j < 4; ++j)
        tile[ty + j * 8][tx] = V[(size_t)(t0 + ty + j * 8) * EE + n0 + tx];
    __syncthreads();
#pragma unroll
    for (int j = 0; j < 4; ++j)
        VT[(size_t)(n0 + ty + j * 8) * TT + t0 + tx] = tile[tx][ty + j * 8];
}

// ---------------------------------------------------------------------------
// Projection: {Q,K,V}h[16384,1024] = Xh @ WTh_z^T + bias_z
// ---------------------------------------------------------------------------
__global__ __launch_bounds__(256, 2) void proj_h(
    const float* __restrict__ b0, const float* __restrict__ b1,
    const float* __restrict__ b2)
{
    __shared__ __align__(16) char sm[4 * TILE_B];
    __shared__ float sbias[128];

    const int tid = threadIdx.x;
    const int z = blockIdx.z;
    const int m0 = blockIdx.y * 128, n0 = blockIdx.x * 128;
    const float* bias = (z == 0) ? b0 : (z == 1) ? b1 : b2;
    half* __restrict__ C = (z == 0) ? g_Qh : (z == 1) ? g_Kh : g_Vh;

    if (tid < 128) sbias[tid] = bias[n0 + tid];

    float acc[4][4][4] = {};
    gemm_body(g_Xh + (size_t)m0 * DD, DD,
              g_WTh + (size_t)z * DD * EE + (size_t)n0 * DD, DD,
              DD / 32, s2u(sm), acc, tid);

    const int warp = tid >> 5, lane = tid & 31;
    const int wm = warp >> 2, wn = warp & 3;
    const int g = lane >> 2, tg = lane & 3;
#pragma unroll
    for (int mi = 0; mi < 4; ++mi) {
        int r0 = m0 + wm * 64 + mi * 16 + g;
#pragma unroll
        for (int ni = 0; ni < 4; ++ni) {
            int cl = wn * 32 + ni * 8 + 2 * tg;
            float bx = sbias[cl], by = sbias[cl + 1];
            int c = n0 + cl;
            *reinterpret_cast<half2*>(&C[(size_t)r0 * EE + c]) =
                __floats2half2_rn(acc[mi][ni][0] + bx, acc[mi][ni][1] + by);
            *reinterpret_cast<half2*>(&C[(size_t)(r0 + 8) * EE + c]) =
                __floats2half2_rn(acc[mi][ni][2] + bx, acc[mi][ni][3] + by);
        }
    }
}

// ---------------------------------------------------------------------------
// Scores: S = (Q @ K^T)/32 on causal blocks (fp32 store); block max -> atomicMax
// ---------------------------------------------------------------------------
__global__ __launch_bounds__(256, 2) void scores_h()
{
    const int bz = blockIdx.z;
    const int t0 = blockIdx.y * 128, s0 = blockIdx.x * 128;
    if (s0 > t0 + 127) return;  // fully masked: never read downstream

    __shared__ __align__(16) char sm[4 * TILE_B];
    __shared__ float red[256];

    const int tid = threadIdx.x;
    float acc[4][4][4] = {};
    gemm_body(g_Qh + ((size_t)bz * TT + t0) * EE, EE,
              g_Kh + ((size_t)bz * TT + s0) * EE, EE,
              EE / 32, s2u(sm), acc, tid);

    float* __restrict__ S = g_S + (size_t)bz * TT * TT;
    const int warp = tid >> 5, lane = tid & 31;
    const int wm = warp >> 2, wn = warp & 3;
    const int g = lane >> 2, tg = lane & 3;

    float lmax = -3.4e38f;
#pragma unroll
    for (int mi = 0; mi < 4; ++mi) {
        int r0 = t0 + wm * 64 + mi * 16 + g;
#pragma unroll
        for (int ni = 0; ni < 4; ++ni) {
            int c = s0 + wn * 32 + ni * 8 + 2 * tg;
#pragma unroll
            for (int half_ : {0, 1}) {
                int r = r0 + half_ * 8;
                float v0 = acc[mi][ni][half_ * 2 + 0] * 0.03125f;
                float v1 = acc[mi][ni][half_ * 2 + 1] * 0.03125f;
                if (c <= r) lmax = fmaxf(lmax, v0); else v0 = -1e30f;
                if (c + 1 <= r) lmax = fmaxf(lmax, v1); else v1 = -1e30f;
                *reinterpret_cast<float2*>(&S[(size_t)r * TT + c]) =
                    make_float2(v0, v1);
            }
        }
    }

    red[tid] = lmax;
    __syncthreads();
    for (int st = 128; st > 0; st >>= 1) {
        if (tid < st) red[tid] = fmaxf(red[tid], red[tid + st]);
        __syncthreads();
    }
    if (tid == 0) atomicMax(&g_max_u[bz], f2mono(red[0]));
}

// ---------------------------------------------------------------------------
// exp(S - m): fp32 sums (deterministic), E stored as half for the V GEMM.
// grid (NCB, BB), triangular block decode.
// ---------------------------------------------------------------------------
__global__ __launch_bounds__(256) void exp_kernel()
{
    const int bz = blockIdx.y;
    const int l = blockIdx.x;
    int tb = (int)((sqrtf(8.0f * l + 1.0f) - 1.0f) * 0.5f);
    while ((tb + 1) * (tb + 2) / 2 <= l) ++tb;
    while (tb * (tb + 1) / 2 > l) --tb;
    const int sbk = l - tb * (tb + 1) / 2;
    const int t0 = tb * 128, s0 = sbk * 128;

    const float m = mono2f(g_max_u[bz]);
    const float* __restrict__ S = g_S + (size_t)bz * TT * TT;
    half* __restrict__ E = g_Eh + (size_t)bz * TT * TT;

    float lsum = 0.0f;
#pragma unroll
    for (int it = 0; it < 16; ++it) {
        int vidx = threadIdx.x + it * 256;
        int r = vidx >> 5, c = (vidx & 31) * 4;
        size_t off = (size_t)(t0 + r) * TT + s0 + c;
        float4 v = *reinterpret_cast<const float4*>(S + off);
        v.x = expf(v.x - m); v.y = expf(v.y - m);
        v.z = expf(v.z - m); v.w = expf(v.w - m);
        lsum += (v.x + v.y) + (v.z + v.w);
        half2 h[2] = {__floats2half2_rn(v.x, v.y), __floats2half2_rn(v.z, v.w)};
        *reinterpret_cast<uint2*>(E + off) = *reinterpret_cast<uint2*>(h);
    }

    __shared__ float red[256];
    red[threadIdx.x] = lsum;
    __syncthreads();
    for (int st = 128; st > 0; st >>= 1) {
        if (threadIdx.x < st) red[threadIdx.x] += red[threadIdx.x + st];
        __syncthreads();
    }
    if (threadIdx.x == 0) g_psum[bz * NCB + l] = red[0];
}

__global__ __launch_bounds__(256) void reduce_kernel()
{
    const int bz = blockIdx.x;
    float s = 0.0f;
    for (int i = threadIdx.x; i < NCB; i += 256) s += g_psum[bz * NCB + i];
    __shared__ float red[256];
    red[threadIdx.x] = s;
    __syncthreads();
    for (int st = 128; st > 0; st >>= 1) {
        if (threadIdx.x < st) red[threadIdx.x] += red[threadIdx.x + st];
        __syncthreads();
    }
    if (threadIdx.x == 0) g_inv_sum[bz] = 1.0f / red[0];
}

// ---------------------------------------------------------------------------
// Output: O = (E @ V) * inv_sum; k-loop truncated at diagonal.
// ---------------------------------------------------------------------------
__global__ __launch_bounds__(256, 2) void out_h(float* __restrict__ O)
{
    const int bz = blockIdx.z;
    const int t0 = blockIdx.y * 128, n0 = blockIdx.x * 128;

    __shared__ __align__(16) char sm[4 * TILE_B];

    const int tid = threadIdx.x;
    float acc[4][4][4] = {};
    gemm_body(g_Eh + ((size_t)bz * TT + t0) * TT, TT,
              g_VTh + ((size_t)bz * EE + n0) * TT, TT,
              (t0 + 128) / 32, s2u(sm), acc, tid);

    const float inv = g_inv_sum[bz];
    const int warp = tid >> 5, lane = tid & 31;
    const int wm = warp >> 2, wn = warp & 3;
    const int g = lane >> 2, tg = lane & 3;
#pragma unroll
    for (int mi = 0; mi < 4; ++mi) {
        int r0 = t0 + wm * 64 + mi * 16 + g;
#pragma unroll
        for (int ni = 0; ni < 4; ++ni) {
            int c = n0 + wn * 32 + ni * 8 + 2 * tg;
            *reinterpret_cast<float2*>(&O[((size_t)bz * TT + r0) * EE + c]) =
                make_float2(acc[mi][ni][0] * inv, acc[mi][ni][1] * inv);
            *reinterpret_cast<float2*>(&O[((size_t)bz * TT + r0 + 8) * EE + c]) =
                make_float2(acc[mi][ni][2] * inv, acc[mi][ni][3] * inv);
        }
    }
}

// ---------------------------------------------------------------------------
extern "C" void kernel_launch(void* const* d_in, const int* in_sizes, int n_in,
                              void* d_out, int out_size)
{
    const float* x  = (const float*)d_in[0];
    const float* Wq = (const float*)d_in[1];
    const float* bq = (const float*)d_in[2];
    const float* Wk = (const float*)d_in[3];
    const float* bk = (const float*)d_in[4];
    const float* Wv = (const float*)d_in[5];
    const float* bv = (const float*)d_in[6];
    float* out = (float*)d_out;

    init_kernel<<<1, 32>>>();
    conv_x<<<8192, 256>>>(x);
    transW_kernel<<<dim3(32, 32, 3), 256>>>(Wq, Wk, Wv);

    proj_h<<<dim3(8, 128, 3), 256>>>(bq, bk, bv);
    transV_kernel<<<dim3(64, 32, 8), 256>>>();

    scores_h<<<dim3(16, 16, 8), 256>>>();

    exp_kernel<<<dim3(NCB, BB), 256>>>();
    reduce_kernel<<<BB, 256>>>();

    out_h<<<dim3(8, 16, 8), 256>>>(out);
}

// round 10
// speedup vs baseline: 2.3861x; 1.0109x over previous
#include <cuda_runtime.h>
#include <cuda_fp16.h>
#include <math.h>
#include <stdint.h>

#define BB 8
#define TT 2048
#define DD 1024
#define EE 1024
#define NCB 136          // causal 128x128 blocks per batch

#define RHB 80           // bytes per smem tile row (32 halves data + pad)
#define TILE_B 10240u    // 128 rows * 80B
#define SMEM3 (6 * 10240)  // 3 stages x (A + B)

// -------- scratch (device globals; allocation-free) --------
__device__ half  g_Xh [(size_t)BB * TT * DD];
__device__ half  g_WTh[(size_t)3 * DD * EE];
__device__ half  g_Qh [(size_t)BB * TT * EE];
__device__ half  g_Kh [(size_t)BB * TT * EE];
__device__ half  g_Vh [(size_t)BB * TT * EE];
__device__ half  g_VTh[(size_t)BB * EE * TT];
__device__ float g_S  [(size_t)BB * TT * TT];
__device__ half  g_Eh [(size_t)BB * TT * TT];
__device__ unsigned g_max_u[BB];
__device__ float g_psum[BB * NCB];
__device__ float g_inv_sum[BB];

// -------- helpers --------
__device__ __forceinline__ unsigned f2mono(float f) {
    unsigned u = __float_as_uint(f);
    return (u & 0x80000000u) ? ~u : (u | 0x80000000u);
}
__device__ __forceinline__ float mono2f(unsigned v) {
    return (v & 0x80000000u) ? __uint_as_float(v ^ 0x80000000u)
                             : __uint_as_float(~v);
}
__device__ __forceinline__ uint32_t s2u(const void* p) {
    return (uint32_t)__cvta_generic_to_shared(p);
}
__device__ __forceinline__ void cpasync16(uint32_t dst, const void* src) {
    asm volatile("cp.async.cg.shared.global [%0], [%1], 16;" :: "r"(dst), "l"(src));
}
__device__ __forceinline__ void cpcommit() {
    asm volatile("cp.async.commit_group;" ::: "memory");
}

#define LDSM4(r0, r1, r2, r3, addr) \
    asm volatile("ldmatrix.sync.aligned.m8n8.x4.shared.b16 {%0,%1,%2,%3}, [%4];" \
        : "=r"(r0), "=r"(r1), "=r"(r2), "=r"(r3) : "r"(addr))

__device__ __forceinline__ void mma16816(float* c, unsigned a0, unsigned a1,
                                         unsigned a2, unsigned a3,
                                         unsigned b0, unsigned b1) {
    asm volatile(
        "mma.sync.aligned.m16n8k16.row.col.f32.f16.f16.f32 "
        "{%0,%1,%2,%3}, {%4,%5,%6,%7}, {%8,%9}, {%0,%1,%2,%3};"
        : "+f"(c[0]), "+f"(c[1]), "+f"(c[2]), "+f"(c[3])
        : "r"(a0), "r"(a1), "r"(a2), "r"(a3), "r"(b0), "r"(b1));
}

// fill one 128x32-half tile (rows RHB bytes apart), coalesced 16B chunks
__device__ __forceinline__ void fill_tile(uint32_t dst, const half* src,
                                          int lds, int tid) {
#pragma unroll
    for (int it = 0; it < 2; ++it) {
        int idx = tid + it * 256;           // 0..511
        int row = idx >> 2, c = idx & 3;    // 4 x 16B per row
        cpasync16(dst + (uint32_t)(row * RHB + c * 16),
                  src + (size_t)row * lds + c * 8);
    }
}

// 3-stage pipelined fp16 GEMM body: 128x128 CTA tile, k-tile 32.
// smem: stage s at su + s*2*TILE_B, layout [A|B]. ONE barrier per k-tile.
__device__ __forceinline__ void gemm_body(
    const half* __restrict__ A0, int lda,
    const half* __restrict__ B0, int ldb,
    int NK, uint32_t su, float acc[4][4][4], int tid)
{
    const int warp = tid >> 5, lane = tid & 31;
    const int wm = warp >> 2, wn = warp & 3;
    const uint32_t aoff = (uint32_t)((wm * 64 + (lane & 15)) * RHB + (lane >> 4) * 16);
    const uint32_t boff = (uint32_t)((wn * 32 + (lane & 7) + ((lane >> 4) << 3)) * RHB
                                     + ((lane >> 3) & 1) * 16);

    fill_tile(su, A0, lda, tid);
    fill_tile(su + TILE_B, B0, ldb, tid);
    cpcommit();
    if (NK > 1) {
        fill_tile(su + 2 * TILE_B, A0 + 32, lda, tid);
        fill_tile(su + 3 * TILE_B, B0 + 32, ldb, tid);
    }
    cpcommit();

    for (int kt = 0; kt < NK; ++kt) {
        // all groups except the newest (fill kt+1) are complete -> stage kt ready
        asm volatile("cp.async.wait_group 1;" ::: "memory");
        __syncthreads();   // also orders: compute(kt-1) done before refilling its stage
        if (kt + 2 < NK) {
            uint32_t nb = su + (uint32_t)((kt + 2) % 3) * (2 * TILE_B);
            fill_tile(nb, A0 + (size_t)(kt + 2) * 32, lda, tid);
            fill_tile(nb + TILE_B, B0 + (size_t)(kt + 2) * 32, ldb, tid);
        }
        cpcommit();

        uint32_t As = su + (uint32_t)(kt % 3) * (2 * TILE_B);
        uint32_t Bs = As + TILE_B;
#pragma unroll
        for (int ks = 0; ks < 2; ++ks) {
            unsigned a[4][4];
#pragma unroll
            for (int mi = 0; mi < 4; ++mi)
                LDSM4(a[mi][0], a[mi][1], a[mi][2], a[mi][3],
                      As + aoff + (uint32_t)(mi * 16 * RHB + ks * 32));
            unsigned b[2][4];
#pragma unroll
            for (int np = 0; np < 2; ++np)
                LDSM4(b[np][0], b[np][1], b[np][2], b[np][3],
                      Bs + boff + (uint32_t)(np * 16 * RHB + ks * 32));
#pragma unroll
            for (int mi = 0; mi < 4; ++mi)
#pragma unroll
                for (int ni = 0; ni < 4; ++ni)
                    mma16816(acc[mi][ni],
                             a[mi][0], a[mi][1], a[mi][2], a[mi][3],
                             b[ni >> 1][(ni & 1) * 2], b[ni >> 1][(ni & 1) * 2 + 1]);
        }
    }
}

// ---------------------------------------------------------------------------
// prep kernels
// ---------------------------------------------------------------------------
__global__ void init_kernel() {
    if (threadIdx.x < BB) g_max_u[threadIdx.x] = 0u;
}

__global__ __launch_bounds__(256) void conv_x(const float* __restrict__ x) {
    size_t i = ((size_t)blockIdx.x * 256 + threadIdx.x) * 8;
    float4 v0 = *reinterpret_cast<const float4*>(x + i);
    float4 v1 = *reinterpret_cast<const float4*>(x + i + 4);
    half2 h[4];
    h[0] = __floats2half2_rn(v0.x, v0.y);
    h[1] = __floats2half2_rn(v0.z, v0.w);
    h[2] = __floats2half2_rn(v1.x, v1.y);
    h[3] = __floats2half2_rn(v1.z, v1.w);
    *reinterpret_cast<uint4*>(g_Xh + i) = *reinterpret_cast<uint4*>(h);
}

// W^T as half: g_WTh[z][n][k] = (half)W_z[k][n]
__global__ __launch_bounds__(256) void transW_kernel(
    const float* __restrict__ W0, const float* __restrict__ W1,
    const float* __restrict__ W2)
{
    const float* W = (blockIdx.z == 0) ? W0 : (blockIdx.z == 1) ? W1 : W2;
    half* WT = g_WTh + (size_t)blockIdx.z * DD * EE;
    __shared__ float tile[32][33];
    int tx = threadIdx.x & 31, ty = threadIdx.x >> 5;
    int k0 = blockIdx.y * 32, n0 = blockIdx.x * 32;
#pragma unroll
    for (int j = 0; j < 4; ++j)
        tile[ty + j * 8][tx] = W[(size_t)(k0 + ty + j * 8) * EE + n0 + tx];
    __syncthreads();
#pragma unroll
    for (int j = 0; j < 4; ++j)
        WT[(size_t)(n0 + ty + j * 8) * DD + k0 + tx] = __float2half(tile[tx][ty + j * 8]);
}

// V^T half: g_VTh[b][n][t] = g_Vh[b][t][n]
__global__ __launch_bounds__(256) void transV_kernel()
{
    const half* V = g_Vh + (size_t)blockIdx.z * TT * EE;
    half* VT = g_VTh + (size_t)blockIdx.z * EE * TT;
    __shared__ half tile[32][34];
    int tx = threadIdx.x & 31, ty = threadIdx.x >> 5;
    int t0 = blockIdx.x * 32, n0 = blockIdx.y * 32;
#pragma unroll
    for (int j = 0; j < 4; ++j)
        tile[ty + j * 8][tx] = V[(size_t)(t0 + ty + j * 8) * EE + n0 + tx];
    __syncthreads();
#pragma unroll
    for (int j = 0; j < 4; ++j)
        VT[(size_t)(n0 + ty + j * 8) * TT + t0 + tx] = tile[tx][ty + j * 8];
}

// ---------------------------------------------------------------------------
// Projection: {Q,K,V}h[16384,1024] = Xh @ WTh_z^T + bias_z
// ---------------------------------------------------------------------------
__global__ __launch_bounds__(256, 2) void proj_h(
    const float* __restrict__ b0, const float* __restrict__ b1,
    const float* __restrict__ b2)
{
    extern __shared__ __align__(16) char sm[];
    __shared__ float sbias[128];

    const int tid = threadIdx.x;
    const int z = blockIdx.z;
    const int m0 = blockIdx.y * 128, n0 = blockIdx.x * 128;
    const float* bias = (z == 0) ? b0 : (z == 1) ? b1 : b2;
    half* __restrict__ C = (z == 0) ? g_Qh : (z == 1) ? g_Kh : g_Vh;

    if (tid < 128) sbias[tid] = bias[n0 + tid];

    float acc[4][4][4] = {};
    gemm_body(g_Xh + (size_t)m0 * DD, DD,
              g_WTh + (size_t)z * DD * EE + (size_t)n0 * DD, DD,
              DD / 32, s2u(sm), acc, tid);

    const int warp = tid >> 5, lane = tid & 31;
    const int wm = warp >> 2, wn = warp & 3;
    const int g = lane >> 2, tg = lane & 3;
#pragma unroll
    for (int mi = 0; mi < 4; ++mi) {
        int r0 = m0 + wm * 64 + mi * 16 + g;
#pragma unroll
        for (int ni = 0; ni < 4; ++ni) {
            int cl = wn * 32 + ni * 8 + 2 * tg;
            float bx = sbias[cl], by = sbias[cl + 1];
            int c = n0 + cl;
            *reinterpret_cast<half2*>(&C[(size_t)r0 * EE + c]) =
                __floats2half2_rn(acc[mi][ni][0] + bx, acc[mi][ni][1] + by);
            *reinterpret_cast<half2*>(&C[(size_t)(r0 + 8) * EE + c]) =
                __floats2half2_rn(acc[mi][ni][2] + bx, acc[mi][ni][3] + by);
        }
    }
}

// ---------------------------------------------------------------------------
// Scores: S = (Q @ K^T)/32 on causal blocks (fp32 store); block max -> atomicMax
// ---------------------------------------------------------------------------
__global__ __launch_bounds__(256, 2) void scores_h()
{
    const int bz = blockIdx.z;
    const int t0 = blockIdx.y * 128, s0 = blockIdx.x * 128;
    if (s0 > t0 + 127) return;  // fully masked: never read downstream

    extern __shared__ __align__(16) char sm[];
    __shared__ float red[256];

    const int tid = threadIdx.x;
    float acc[4][4][4] = {};
    gemm_body(g_Qh + ((size_t)bz * TT + t0) * EE, EE,
              g_Kh + ((size_t)bz * TT + s0) * EE, EE,
              EE / 32, s2u(sm), acc, tid);

    float* __restrict__ S = g_S + (size_t)bz * TT * TT;
    const int warp = tid >> 5, lane = tid & 31;
    const int wm = warp >> 2, wn = warp & 3;
    const int g = lane >> 2, tg = lane & 3;

    float lmax = -3.4e38f;
#pragma unroll
    for (int mi = 0; mi < 4; ++mi) {
        int r0 = t0 + wm * 64 + mi * 16 + g;
#pragma unroll
        for (int ni = 0; ni < 4; ++ni) {
            int c = s0 + wn * 32 + ni * 8 + 2 * tg;
#pragma unroll
            for (int half_ : {0, 1}) {
                int r = r0 + half_ * 8;
                float v0 = acc[mi][ni][half_ * 2 + 0] * 0.03125f;
                float v1 = acc[mi][ni][half_ * 2 + 1] * 0.03125f;
                if (c <= r) lmax = fmaxf(lmax, v0); else v0 = -1e30f;
                if (c + 1 <= r) lmax = fmaxf(lmax, v1); else v1 = -1e30f;
                *reinterpret_cast<float2*>(&S[(size_t)r * TT + c]) =
                    make_float2(v0, v1);
            }
        }
    }

    red[tid] = lmax;
    __syncthreads();
    for (int st = 128; st > 0; st >>= 1) {
        if (tid < st) red[tid] = fmaxf(red[tid], red[tid + st]);
        __syncthreads();
    }
    if (tid == 0) atomicMax(&g_max_u[bz], f2mono(red[0]));
}

// ---------------------------------------------------------------------------
// exp(S - m): fp32 sums (deterministic), E stored as half for the V GEMM.
// grid (NCB, BB), triangular block decode.
// ---------------------------------------------------------------------------
__global__ __launch_bounds__(256) void exp_kernel()
{
    const int bz = blockIdx.y;
    const int l = blockIdx.x;
    int tb = (int)((sqrtf(8.0f * l + 1.0f) - 1.0f) * 0.5f);
    while ((tb + 1) * (tb + 2) / 2 <= l) ++tb;
    while (tb * (tb + 1) / 2 > l) --tb;
    const int sbk = l - tb * (tb + 1) / 2;
    const int t0 = tb * 128, s0 = sbk * 128;

    const float m = mono2f(g_max_u[bz]);
    const float* __restrict__ S = g_S + (size_t)bz * TT * TT;
    half* __restrict__ E = g_Eh + (size_t)bz * TT * TT;

    float lsum = 0.0f;
#pragma unroll
    for (int it = 0; it < 16; ++it) {
        int vidx = threadIdx.x + it * 256;
        int r = vidx >> 5, c = (vidx & 31) * 4;
        size_t off = (size_t)(t0 + r) * TT + s0 + c;
        float4 v = *reinterpret_cast<const float4*>(S + off);
        v.x = expf(v.x - m); v.y = expf(v.y - m);
        v.z = expf(v.z - m); v.w = expf(v.w - m);
        lsum += (v.x + v.y) + (v.z + v.w);
        half2 h[2] = {__floats2half2_rn(v.x, v.y), __floats2half2_rn(v.z, v.w)};
        *reinterpret_cast<uint2*>(E + off) = *reinterpret_cast<uint2*>(h);
    }

    __shared__ float red[256];
    red[threadIdx.x] = lsum;
    __syncthreads();
    for (int st = 128; st > 0; st >>= 1) {
        if (threadIdx.x < st) red[threadIdx.x] += red[threadIdx.x + st];
        __syncthreads();
    }
    if (threadIdx.x == 0) g_psum[bz * NCB + l] = red[0];
}

__global__ __launch_bounds__(256) void reduce_kernel()
{
    const int bz = blockIdx.x;
    float s = 0.0f;
    for (int i = threadIdx.x; i < NCB; i += 256) s += g_psum[bz * NCB + i];
    __shared__ float red[256];
    red[threadIdx.x] = s;
    __syncthreads();
    for (int st = 128; st > 0; st >>= 1) {
        if (threadIdx.x < st) red[threadIdx.x] += red[threadIdx.x + st];
        __syncthreads();
    }
    if (threadIdx.x == 0) g_inv_sum[bz] = 1.0f / red[0];
}

// ---------------------------------------------------------------------------
// Output: O = (E @ V) * inv_sum; k-loop truncated at diagonal.
// ---------------------------------------------------------------------------
__global__ __launch_bounds__(256, 2) void out_h(float* __restrict__ O)
{
    const int bz = blockIdx.z;
    const int t0 = blockIdx.y * 128, n0 = blockIdx.x * 128;

    extern __shared__ __align__(16) char sm[];

    const int tid = threadIdx.x;
    float acc[4][4][4] = {};
    gemm_body(g_Eh + ((size_t)bz * TT + t0) * TT, TT,
              g_VTh + ((size_t)bz * EE + n0) * TT, TT,
              (t0 + 128) / 32, s2u(sm), acc, tid);

    const float inv = g_inv_sum[bz];
    const int warp = tid >> 5, lane = tid & 31;
    const int wm = warp >> 2, wn = warp & 3;
    const int g = lane >> 2, tg = lane & 3;
#pragma unroll
    for (int mi = 0; mi < 4; ++mi) {
        int r0 = t0 + wm * 64 + mi * 16 + g;
#pragma unroll
        for (int ni = 0; ni < 4; ++ni) {
            int c = n0 + wn * 32 + ni * 8 + 2 * tg;
            *reinterpret_cast<float2*>(&O[((size_t)bz * TT + r0) * EE + c]) =
                make_float2(acc[mi][ni][0] * inv, acc[mi][ni][1] * inv);
            *reinterpret_cast<float2*>(&O[((size_t)bz * TT + r0 + 8) * EE + c]) =
                make_float2(acc[mi][ni][2] * inv, acc[mi][ni][3] * inv);
        }
    }
}

// ---------------------------------------------------------------------------
extern "C" void kernel_launch(void* const* d_in, const int* in_sizes, int n_in,
                              void* d_out, int out_size)
{
    const float* x  = (const float*)d_in[0];
    const float* Wq = (const float*)d_in[1];
    const float* bq = (const float*)d_in[2];
    const float* Wk = (const float*)d_in[3];
    const float* bk = (const float*)d_in[4];
    const float* Wv = (const float*)d_in[5];
    const float* bv = (const float*)d_in[6];
    float* out = (float*)d_out;

    static bool attr_done = false;
    if (!attr_done) {
        cudaFuncSetAttribute(proj_h,
            cudaFuncAttributeMaxDynamicSharedMemorySize, SMEM3);
        cudaFuncSetAttribute(scores_h,
            cudaFuncAttributeMaxDynamicSharedMemorySize, SMEM3);
        cudaFuncSetAttribute(out_h,
            cudaFuncAttributeMaxDynamicSharedMemorySize, SMEM3);
        attr_done = true;
    }

    init_kernel<<<1, 32>>>();
    conv_x<<<8192, 256>>>(x);
    transW_kernel<<<dim3(32, 32, 3), 256>>>(Wq, Wk, Wv);

    proj_h<<<dim3(8, 128, 3), 256, SMEM3>>>(bq, bk, bv);
    transV_kernel<<<dim3(64, 32, 8), 256>>>();

    scores_h<<<dim3(16, 16, 8), 256, SMEM3>>>();

    exp_kernel<<<dim3(NCB, BB), 256>>>();
    reduce_kernel<<<BB, 256>>>();

    out_h<<<dim3(8, 16, 8), 256, SMEM3>>>(out);
}